// round 8
// baseline (speedup 1.0000x reference)
#include <cuda_runtime.h>
#include <cuda_bf16.h>
#include <cstdint>

// ============================================================
// Problem sizes
// ============================================================
#define BATCH   4096
#define IN_SZ   2048
#define HID     4096
#define NCLS    1000
#define NCLSP   1024   // padded N for layer 3

// ============================================================
// Device scratch (allocation-free rule: __device__ globals)
// ============================================================
__device__ __nv_bfloat16 g_Xh [(size_t)BATCH * IN_SZ];
__device__ __nv_bfloat16 g_Xl [(size_t)BATCH * IN_SZ];
__device__ __nv_bfloat16 g_W1h[(size_t)HID   * IN_SZ];   // [N=HID, K=IN_SZ] K-major
__device__ __nv_bfloat16 g_W1l[(size_t)HID   * IN_SZ];
__device__ __nv_bfloat16 g_W2h[(size_t)HID   * HID];
__device__ __nv_bfloat16 g_W2l[(size_t)HID   * HID];
__device__ __nv_bfloat16 g_W3h[(size_t)NCLSP * HID];
__device__ __nv_bfloat16 g_W3l[(size_t)NCLSP * HID];
__device__ __nv_bfloat16 g_H1h[(size_t)BATCH * HID];
__device__ __nv_bfloat16 g_H1l[(size_t)BATCH * HID];
__device__ __nv_bfloat16 g_H2h[(size_t)BATCH * HID];
__device__ __nv_bfloat16 g_H2l[(size_t)BATCH * HID];

// ============================================================
// Baseline-target PTX helpers (NO a-suffix features)
// ============================================================
__device__ __forceinline__ uint32_t smem_u32(const void* p) {
    uint32_t a;
    asm("{ .reg .u64 t; cvta.to.shared.u64 t, %1; cvt.u32.u64 %0, t; }"
        : "=r"(a) : "l"(p));
    return a;
}

#define CP_ASYNC16(dst, src) \
    asm volatile("cp.async.cg.shared.global [%0], [%1], 16;" \
        :: "r"(dst), "l"(src) : "memory")
#define CP_COMMIT() asm volatile("cp.async.commit_group;" ::: "memory")
#define CP_WAIT(n)  asm volatile("cp.async.wait_group %0;" :: "n"(n) : "memory")

#define LDSM4(r0, r1, r2, r3, addr) \
    asm volatile("ldmatrix.sync.aligned.m8n8.x4.shared.b16 {%0,%1,%2,%3}, [%4];" \
        : "=r"(r0), "=r"(r1), "=r"(r2), "=r"(r3) : "r"(addr))

#define MMA16816(d, a0, a1, a2, a3, b0, b1) \
    asm volatile("mma.sync.aligned.m16n8k16.row.col.f32.bf16.bf16.f32 " \
        "{%0,%1,%2,%3}, {%4,%5,%6,%7}, {%8,%9}, {%0,%1,%2,%3};" \
        : "+f"((d)[0]), "+f"((d)[1]), "+f"((d)[2]), "+f"((d)[3]) \
        : "r"(a0), "r"(a1), "r"(a2), "r"(a3), "r"(b0), "r"(b1))

__device__ __forceinline__ void split2(float v, __nv_bfloat16& h, __nv_bfloat16& l) {
    h = __float2bfloat16_rn(v);
    l = __float2bfloat16_rn(v - __bfloat162float(h));
}

// ============================================================
// Pre-pass 1: elementwise split fp32 -> (hi, lo) bf16
// ============================================================
__global__ void __launch_bounds__(256)
split_kernel(const float* __restrict__ in, __nv_bfloat16* __restrict__ oh,
             __nv_bfloat16* __restrict__ ol, int n4)
{
    int i = blockIdx.x * 256 + threadIdx.x;
    if (i >= n4) return;
    float4 v = reinterpret_cast<const float4*>(in)[i];
    __nv_bfloat16 h0, h1, h2, h3, l0, l1, l2, l3;
    split2(v.x, h0, l0); split2(v.y, h1, l1); split2(v.z, h2, l2); split2(v.w, h3, l3);
    __nv_bfloat162* oh2 = reinterpret_cast<__nv_bfloat162*>(oh);
    __nv_bfloat162* ol2 = reinterpret_cast<__nv_bfloat162*>(ol);
    oh2[i * 2 + 0] = __nv_bfloat162(h0, h1);
    oh2[i * 2 + 1] = __nv_bfloat162(h2, h3);
    ol2[i * 2 + 0] = __nv_bfloat162(l0, l1);
    ol2[i * 2 + 1] = __nv_bfloat162(l2, l3);
}

// ============================================================
// Pre-pass 2: transpose [K,N] fp32 -> [Npad,K] (hi,lo) bf16 (zero-pad n>=N)
// ============================================================
__global__ void __launch_bounds__(256)
transpose_split_kernel(const float* __restrict__ w, __nv_bfloat16* __restrict__ oh,
                       __nv_bfloat16* __restrict__ ol, int K, int N, int Npad)
{
    __shared__ float t[32][33];
    int n0 = blockIdx.x * 32;
    int k0 = blockIdx.y * 32;
    #pragma unroll
    for (int r = threadIdx.y; r < 32; r += 8) {
        int n = n0 + threadIdx.x;
        float v = 0.0f;
        if (n < N) v = w[(size_t)(k0 + r) * N + n];
        t[r][threadIdx.x] = v;
    }
    __syncthreads();
    #pragma unroll
    for (int r = threadIdx.y; r < 32; r += 8) {
        int n = n0 + r;
        int k = k0 + threadIdx.x;
        float v = t[threadIdx.x][r];
        __nv_bfloat16 h, l;
        split2(v, h, l);
        oh[(size_t)n * K + k] = h;
        ol[(size_t)n * K + k] = l;
    }
}

// ============================================================
// GEMM: C[M,N] = op(A @ B^T + bias), split-bf16 3-term accumulation
//   A: (Ah,Al) [M,K] K-major;  B: (Bh,Bl) [N,K] K-major
// CTA tile 128x256, K-chunk 32, 3-stage cp.async pipeline.
// 512 threads = 16 warps in 2(M) x 8(N); warp tile 64x32.
// SMEM rows padded to 80 B (32 bf16 + 8 pad) -> conflict-free ldmatrix.
// ============================================================
#define ROWB        80
#define TILE_M      128
#define TILE_N      256
#define OFF_AH      0
#define OFF_AL      (TILE_M * ROWB)                 // 10240
#define OFF_BH      (2 * TILE_M * ROWB)             // 20480
#define OFF_BL      (2 * TILE_M * ROWB + TILE_N * ROWB)   // 40960
#define STAGE_BYTES ((2 * TILE_M + 2 * TILE_N) * ROWB)    // 61440
#define NSTAGE      3
#define SMEM_TOTAL  (NSTAGE * STAGE_BYTES)          // 184320

__global__ void __launch_bounds__(512, 1)
gemm_split_kernel(const __nv_bfloat16* __restrict__ Ah, const __nv_bfloat16* __restrict__ Al,
                  const __nv_bfloat16* __restrict__ Bh, const __nv_bfloat16* __restrict__ Bl,
                  const float* __restrict__ bias,
                  float* __restrict__ Cf,
                  __nv_bfloat16* __restrict__ Ch, __nv_bfloat16* __restrict__ Cl,
                  int M, int N, int K, int Nreal, int do_relu, int split_out)
{
    extern __shared__ char smem[];
    const uint32_t sbase = smem_u32(smem);
    const int tid  = threadIdx.x;
    const int wid  = tid >> 5;
    const int lane = tid & 31;
    const int wm   = wid >> 3;   // 0..1 (M)
    const int wn   = wid & 7;    // 0..7 (N)

    // ---- block swizzle for L2 locality ----
    const int tiles_n = N / TILE_N;
    const int tiles_m = M / TILE_M;
    const int G = 8;
    const int bpg = G * tiles_n;
    const int group = blockIdx.x / bpg;
    const int rem = blockIdx.x - group * bpg;
    int gsz = tiles_m - group * G; if (gsz > G) gsz = G;
    const int tm = group * G + rem % gsz;
    const int tn = rem / gsz;
    const int m0 = tm * TILE_M;
    const int n0 = tn * TILE_N;

    // loader mapping: A arrays 128 rows x 4 cols (1 cp each), B arrays 256 rows x 2 cols
    const int a_r = tid >> 2;            // 0..127
    const int a_c = tid & 3;             // 0..3
    const int b_r = tid >> 1;            // 0..255
    const int b_c = (tid & 1) * 2;       // 0 or 2

    // ldmatrix per-lane addressing
    const uint32_t lrow16 = (uint32_t)(lane & 15) * ROWB + (uint32_t)(lane >> 4) * 16;
    const uint32_t aFragOff = (uint32_t)(wm * 64) * ROWB + lrow16;
    const uint32_t bFragOff = (uint32_t)(wn * 32) * ROWB + lrow16;

    float acc[4][4][4];
    #pragma unroll
    for (int mt = 0; mt < 4; ++mt)
        #pragma unroll
        for (int nt = 0; nt < 4; ++nt)
            #pragma unroll
            for (int e = 0; e < 4; ++e) acc[mt][nt][e] = 0.0f;

    const int nch = K >> 5;

    auto load_stage = [&](int chunk, int buf) {
        const int kb = chunk << 5;
        const uint32_t sg = sbase + (uint32_t)buf * STAGE_BYTES;
        const uint32_t sa = sg + (uint32_t)a_r * ROWB + (uint32_t)a_c * 16;
        const size_t gA = (size_t)(m0 + a_r) * K + kb + a_c * 8;
        CP_ASYNC16(sa + OFF_AH, Ah + gA);
        CP_ASYNC16(sa + OFF_AL, Al + gA);
        const uint32_t sb = sg + (uint32_t)b_r * ROWB + (uint32_t)b_c * 16;
        const size_t gB = (size_t)(n0 + b_r) * K + kb + b_c * 8;
        CP_ASYNC16(sb + OFF_BH,      Bh + gB);
        CP_ASYNC16(sb + OFF_BH + 16, Bh + gB + 8);
        CP_ASYNC16(sb + OFF_BL,      Bl + gB);
        CP_ASYNC16(sb + OFF_BL + 16, Bl + gB + 8);
    };

    load_stage(0, 0); CP_COMMIT();
    load_stage(1, 1); CP_COMMIT();

    int buf = 0;
    for (int c = 0; c < nch; ++c) {
        if (c == nch - 1) { CP_WAIT(0); } else { CP_WAIT(1); }
        __syncthreads();

        const uint32_t sg = sbase + (uint32_t)buf * STAGE_BYTES;
        #pragma unroll
        for (int ks = 0; ks < 2; ++ks) {
            const uint32_t ko = (uint32_t)ks * 32;
            uint32_t ah[4][4], al[4][4];
            #pragma unroll
            for (int mt = 0; mt < 4; ++mt) {
                const uint32_t a = sg + aFragOff + (uint32_t)mt * (16 * ROWB) + ko;
                LDSM4(ah[mt][0], ah[mt][1], ah[mt][2], ah[mt][3], a + OFF_AH);
                LDSM4(al[mt][0], al[mt][1], al[mt][2], al[mt][3], a + OFF_AL);
            }
            #pragma unroll
            for (int ntp = 0; ntp < 2; ++ntp) {
                const uint32_t b = sg + bFragOff + (uint32_t)ntp * (16 * ROWB) + ko;
                uint32_t h0, h1, h2, h3, l0, l1, l2, l3;
                LDSM4(h0, h1, h2, h3, b + OFF_BH);
                LDSM4(l0, l1, l2, l3, b + OFF_BL);
                const int ne = 2 * ntp, no = 2 * ntp + 1;
                #pragma unroll
                for (int mt = 0; mt < 4; ++mt) {
                    MMA16816(acc[mt][ne], ah[mt][0], ah[mt][1], ah[mt][2], ah[mt][3], h0, h2);
                    MMA16816(acc[mt][no], ah[mt][0], ah[mt][1], ah[mt][2], ah[mt][3], h1, h3);
                    MMA16816(acc[mt][ne], ah[mt][0], ah[mt][1], ah[mt][2], ah[mt][3], l0, l2);
                    MMA16816(acc[mt][no], ah[mt][0], ah[mt][1], ah[mt][2], ah[mt][3], l1, l3);
                    MMA16816(acc[mt][ne], al[mt][0], al[mt][1], al[mt][2], al[mt][3], h0, h2);
                    MMA16816(acc[mt][no], al[mt][0], al[mt][1], al[mt][2], al[mt][3], h1, h3);
                }
            }
        }

        const int nx = c + NSTAGE - 1;
        if (nx < nch) { load_stage(nx, nx % NSTAGE); CP_COMMIT(); }
        buf = (buf + 1 == NSTAGE) ? 0 : buf + 1;
    }

    // ---- epilogue: bias (+relu) fused; split-bf16 or fp32 out ----
    const int mrow = lane >> 2;
    const int ncol = (lane & 3) * 2;
    #pragma unroll
    for (int mt = 0; mt < 4; ++mt) {
        #pragma unroll
        for (int nt = 0; nt < 4; ++nt) {
            const int n = n0 + wn * 32 + nt * 8 + ncol;
            float bx = 0.0f, by = 0.0f;
            if (split_out) {
                float2 bv = *reinterpret_cast<const float2*>(bias + n);
                bx = bv.x; by = bv.y;
            } else {
                if (n     < Nreal) bx = bias[n];
                if (n + 1 < Nreal) by = bias[n + 1];
            }
            #pragma unroll
            for (int half = 0; half < 2; ++half) {
                const int m = m0 + wm * 64 + mt * 16 + mrow + half * 8;
                float v0 = acc[mt][nt][half * 2 + 0] + bx;
                float v1 = acc[mt][nt][half * 2 + 1] + by;
                if (do_relu) {
                    v0 = v0 > 0.0f ? v0 : 0.0f;
                    v1 = v1 > 0.0f ? v1 : 0.0f;
                }
                if (split_out) {
                    __nv_bfloat16 h0, q0, h1, q1;
                    split2(v0, h0, q0); split2(v1, h1, q1);
                    *reinterpret_cast<__nv_bfloat162*>(Ch + (size_t)m * N + n) =
                        __nv_bfloat162(h0, h1);
                    *reinterpret_cast<__nv_bfloat162*>(Cl + (size_t)m * N + n) =
                        __nv_bfloat162(q0, q1);
                } else {
                    if (n     < Nreal) Cf[(size_t)m * Nreal + n]     = v0;
                    if (n + 1 < Nreal) Cf[(size_t)m * Nreal + n + 1] = v1;
                }
            }
        }
    }
}

// ============================================================
// Launch
// ============================================================
extern "C" void kernel_launch(void* const* d_in, const int* in_sizes, int n_in,
                              void* d_out, int out_size)
{
    const float* x  = (const float*)d_in[0];
    const float* w1 = (const float*)d_in[1];
    const float* b1 = (const float*)d_in[2];
    const float* w2 = (const float*)d_in[3];
    const float* b2 = (const float*)d_in[4];
    const float* w3 = (const float*)d_in[5];
    const float* b3 = (const float*)d_in[6];
    float* out = (float*)d_out;

    void *pXh, *pXl, *pW1h, *pW1l, *pW2h, *pW2l, *pW3h, *pW3l, *pH1h, *pH1l, *pH2h, *pH2l;
    cudaGetSymbolAddress(&pXh, g_Xh);   cudaGetSymbolAddress(&pXl, g_Xl);
    cudaGetSymbolAddress(&pW1h, g_W1h); cudaGetSymbolAddress(&pW1l, g_W1l);
    cudaGetSymbolAddress(&pW2h, g_W2h); cudaGetSymbolAddress(&pW2l, g_W2l);
    cudaGetSymbolAddress(&pW3h, g_W3h); cudaGetSymbolAddress(&pW3l, g_W3l);
    cudaGetSymbolAddress(&pH1h, g_H1h); cudaGetSymbolAddress(&pH1l, g_H1l);
    cudaGetSymbolAddress(&pH2h, g_H2h); cudaGetSymbolAddress(&pH2l, g_H2l);

    cudaFuncSetAttribute(gemm_split_kernel,
                         cudaFuncAttributeMaxDynamicSharedMemorySize, SMEM_TOTAL);

    // --- pre-pass: split x; transpose+split weights ---
    {
        int n4 = (BATCH * IN_SZ) / 4;
        split_kernel<<<(n4 + 255) / 256, 256>>>(
            x, (__nv_bfloat16*)pXh, (__nv_bfloat16*)pXl, n4);
    }
    transpose_split_kernel<<<dim3(HID / 32, IN_SZ / 32), dim3(32, 8)>>>(
        w1, (__nv_bfloat16*)pW1h, (__nv_bfloat16*)pW1l, IN_SZ, HID, HID);
    transpose_split_kernel<<<dim3(HID / 32, HID / 32), dim3(32, 8)>>>(
        w2, (__nv_bfloat16*)pW2h, (__nv_bfloat16*)pW2l, HID, HID, HID);
    transpose_split_kernel<<<dim3(NCLSP / 32, HID / 32), dim3(32, 8)>>>(
        w3, (__nv_bfloat16*)pW3h, (__nv_bfloat16*)pW3l, HID, NCLS, NCLSP);

    // --- layer 1: h1 = relu(x @ w1 + b1), split-bf16 out ---
    gemm_split_kernel<<<(BATCH / TILE_M) * (HID / TILE_N), 512, SMEM_TOTAL>>>(
        (const __nv_bfloat16*)pXh, (const __nv_bfloat16*)pXl,
        (const __nv_bfloat16*)pW1h, (const __nv_bfloat16*)pW1l,
        b1, nullptr, (__nv_bfloat16*)pH1h, (__nv_bfloat16*)pH1l,
        BATCH, HID, IN_SZ, HID, 1, 1);

    // --- layer 2: h2 = relu(h1 @ w2 + b2), split-bf16 out ---
    gemm_split_kernel<<<(BATCH / TILE_M) * (HID / TILE_N), 512, SMEM_TOTAL>>>(
        (const __nv_bfloat16*)pH1h, (const __nv_bfloat16*)pH1l,
        (const __nv_bfloat16*)pW2h, (const __nv_bfloat16*)pW2l,
        b2, nullptr, (__nv_bfloat16*)pH2h, (__nv_bfloat16*)pH2l,
        BATCH, HID, HID, HID, 1, 1);

    // --- layer 3: out = h2 @ w3 + b3, fp32 out (N padded 1024 -> 1000) ---
    gemm_split_kernel<<<(BATCH / TILE_M) * (NCLSP / TILE_N), 512, SMEM_TOTAL>>>(
        (const __nv_bfloat16*)pH2h, (const __nv_bfloat16*)pH2l,
        (const __nv_bfloat16*)pW3h, (const __nv_bfloat16*)pW3l,
        b3, out, nullptr, nullptr,
        BATCH, NCLSP, HID, NCLS, 0, 0);
}

// round 9
// speedup vs baseline: 1.2405x; 1.2405x over previous
#include <cuda_runtime.h>
#include <cuda_bf16.h>
#include <cstdint>

// ============================================================
// Problem sizes
// ============================================================
#define BATCH   4096
#define IN_SZ   2048
#define HID     4096
#define NCLS    1000
#define NCLSP   1024   // padded N for layer 3

// ============================================================
// Device scratch (allocation-free rule: __device__ globals)
// ============================================================
__device__ __nv_bfloat16 g_Xh [(size_t)BATCH * IN_SZ];
__device__ __nv_bfloat16 g_Xl [(size_t)BATCH * IN_SZ];
__device__ __nv_bfloat16 g_W1h[(size_t)HID   * IN_SZ];   // [N=HID, K=IN_SZ] K-major
__device__ __nv_bfloat16 g_W1l[(size_t)HID   * IN_SZ];
__device__ __nv_bfloat16 g_W2h[(size_t)HID   * HID];
__device__ __nv_bfloat16 g_W2l[(size_t)HID   * HID];
__device__ __nv_bfloat16 g_W3h[(size_t)NCLSP * HID];
__device__ __nv_bfloat16 g_W3l[(size_t)NCLSP * HID];
__device__ __nv_bfloat16 g_H1h[(size_t)BATCH * HID];
__device__ __nv_bfloat16 g_H1l[(size_t)BATCH * HID];
__device__ __nv_bfloat16 g_H2h[(size_t)BATCH * HID];
__device__ __nv_bfloat16 g_H2l[(size_t)BATCH * HID];

// ============================================================
// Baseline-target PTX helpers (NO a-suffix features)
// ============================================================
__device__ __forceinline__ uint32_t smem_u32(const void* p) {
    uint32_t a;
    asm("{ .reg .u64 t; cvta.to.shared.u64 t, %1; cvt.u32.u64 %0, t; }"
        : "=r"(a) : "l"(p));
    return a;
}

#define CP_ASYNC16(dst, src) \
    asm volatile("cp.async.cg.shared.global [%0], [%1], 16;" \
        :: "r"(dst), "l"(src) : "memory")
#define CP_COMMIT() asm volatile("cp.async.commit_group;" ::: "memory")
#define CP_WAIT(n)  asm volatile("cp.async.wait_group %0;" :: "n"(n) : "memory")

#define LDSM4(r0, r1, r2, r3, addr) \
    asm volatile("ldmatrix.sync.aligned.m8n8.x4.shared.b16 {%0,%1,%2,%3}, [%4];" \
        : "=r"(r0), "=r"(r1), "=r"(r2), "=r"(r3) : "r"(addr))

#define MMA16816(d, a, b) \
    asm volatile("mma.sync.aligned.m16n8k16.row.col.f32.bf16.bf16.f32 " \
        "{%0,%1,%2,%3}, {%4,%5,%6,%7}, {%8,%9}, {%0,%1,%2,%3};" \
        : "+f"((d)[0]), "+f"((d)[1]), "+f"((d)[2]), "+f"((d)[3]) \
        : "r"((a)[0]), "r"((a)[1]), "r"((a)[2]), "r"((a)[3]), \
          "r"((b)[0]), "r"((b)[1]))

__device__ __forceinline__ void split2(float v, __nv_bfloat16& h, __nv_bfloat16& l) {
    h = __float2bfloat16_rn(v);
    l = __float2bfloat16_rn(v - __bfloat162float(h));
}

// ============================================================
// Pre-pass 1: elementwise split fp32 -> (hi, lo) bf16
// ============================================================
__global__ void __launch_bounds__(256)
split_kernel(const float* __restrict__ in, __nv_bfloat16* __restrict__ oh,
             __nv_bfloat16* __restrict__ ol, int n4)
{
    int i = blockIdx.x * 256 + threadIdx.x;
    if (i >= n4) return;
    float4 v = reinterpret_cast<const float4*>(in)[i];
    __nv_bfloat16 h0, h1, h2, h3, l0, l1, l2, l3;
    split2(v.x, h0, l0); split2(v.y, h1, l1); split2(v.z, h2, l2); split2(v.w, h3, l3);
    __nv_bfloat162* oh2 = reinterpret_cast<__nv_bfloat162*>(oh);
    __nv_bfloat162* ol2 = reinterpret_cast<__nv_bfloat162*>(ol);
    oh2[i * 2 + 0] = __nv_bfloat162(h0, h1);
    oh2[i * 2 + 1] = __nv_bfloat162(h2, h3);
    ol2[i * 2 + 0] = __nv_bfloat162(l0, l1);
    ol2[i * 2 + 1] = __nv_bfloat162(l2, l3);
}

// ============================================================
// Pre-pass 2: transpose [K,N] fp32 -> [Npad,K] (hi,lo) bf16 (zero-pad n>=N)
// ============================================================
__global__ void __launch_bounds__(256)
transpose_split_kernel(const float* __restrict__ w, __nv_bfloat16* __restrict__ oh,
                       __nv_bfloat16* __restrict__ ol, int K, int N, int Npad)
{
    __shared__ float t[32][33];
    int n0 = blockIdx.x * 32;
    int k0 = blockIdx.y * 32;
    #pragma unroll
    for (int r = threadIdx.y; r < 32; r += 8) {
        int n = n0 + threadIdx.x;
        float v = 0.0f;
        if (n < N) v = w[(size_t)(k0 + r) * N + n];
        t[r][threadIdx.x] = v;
    }
    __syncthreads();
    #pragma unroll
    for (int r = threadIdx.y; r < 32; r += 8) {
        int n = n0 + r;
        int k = k0 + threadIdx.x;
        float v = t[threadIdx.x][r];
        __nv_bfloat16 h, l;
        split2(v, h, l);
        oh[(size_t)n * K + k] = h;
        ol[(size_t)n * K + k] = l;
    }
}

// ============================================================
// GEMM: C[M,N] = op(A @ B^T + bias), split-bf16 3-term accumulation
//   A: (Ah,Al) [M,K] K-major;  B: (Bh,Bl) [N,K] K-major
// CTA tile 128x128, K-chunk 64, 3-stage cp.async pipeline.
// 512 threads = 16 warps in 4(M) x 4(N); warp tile 32x32 (no reg spill).
// SMEM rows padded to 144 B (64 bf16 data + 16 pad) -> conflict-free ldmatrix
// (row offsets r*144 mod 128 = 16r: 8 distinct 16B slots per 8-row phase).
// ============================================================
#define ROWB        144
#define KC          64
#define OFF_AH      0
#define OFF_AL      (128 * ROWB)            // 18432
#define OFF_BH      (2 * 128 * ROWB)
#define OFF_BL      (3 * 128 * ROWB)
#define STAGE_BYTES (4 * 128 * ROWB)        // 73728
#define NSTAGE      3
#define SMEM_TOTAL  (NSTAGE * STAGE_BYTES)  // 221184

__global__ void __launch_bounds__(512, 1)
gemm_split_kernel(const __nv_bfloat16* __restrict__ Ah, const __nv_bfloat16* __restrict__ Al,
                  const __nv_bfloat16* __restrict__ Bh, const __nv_bfloat16* __restrict__ Bl,
                  const float* __restrict__ bias,
                  float* __restrict__ Cf,
                  __nv_bfloat16* __restrict__ Ch, __nv_bfloat16* __restrict__ Cl,
                  int M, int N, int K, int Nreal, int do_relu, int split_out)
{
    extern __shared__ char smem[];
    const uint32_t sbase = smem_u32(smem);
    const int tid  = threadIdx.x;
    const int wid  = tid >> 5;
    const int lane = tid & 31;
    const int wm   = wid >> 2;   // 0..3
    const int wn   = wid & 3;    // 0..3

    // ---- block swizzle for L2 locality ----
    const int tiles_n = N >> 7;
    const int tiles_m = M >> 7;
    const int G = 8;
    const int bpg = G * tiles_n;
    const int group = blockIdx.x / bpg;
    const int rem = blockIdx.x - group * bpg;
    int gsz = tiles_m - group * G; if (gsz > G) gsz = G;
    const int tm = group * G + rem % gsz;
    const int tn = rem / gsz;
    const int m0 = tm << 7;
    const int n0 = tn << 7;

    // loader mapping: per array 128 rows x 8 cols of 16B; thread covers
    // (row, col) and (row+64, col).
    const int ld_r = tid >> 3;    // 0..63
    const int ld_c = tid & 7;     // 0..7

    // ldmatrix per-lane addressing
    const uint32_t lrow16 = (uint32_t)(lane & 15) * ROWB + (uint32_t)(lane >> 4) * 16;
    const uint32_t aFragOff = (uint32_t)(wm * 32) * ROWB + lrow16;
    const uint32_t bFragOff = (uint32_t)(wn * 32) * ROWB + lrow16;

    float acc[2][4][4];
    #pragma unroll
    for (int mt = 0; mt < 2; ++mt)
        #pragma unroll
        for (int nt = 0; nt < 4; ++nt)
            #pragma unroll
            for (int e = 0; e < 4; ++e) acc[mt][nt][e] = 0.0f;

    const int nch = K / KC;

    auto load_stage = [&](int chunk, int buf) {
        const int kb = chunk * KC;
        const uint32_t s0 = sbase + (uint32_t)buf * STAGE_BYTES
                          + (uint32_t)ld_r * ROWB + (uint32_t)ld_c * 16;
        const uint32_t s1 = s0 + 64 * ROWB;
        const size_t gA0 = (size_t)(m0 + ld_r) * K + kb + ld_c * 8;
        const size_t gA1 = gA0 + (size_t)64 * K;
        const size_t gB0 = (size_t)(n0 + ld_r) * K + kb + ld_c * 8;
        const size_t gB1 = gB0 + (size_t)64 * K;
        CP_ASYNC16(s0 + OFF_AH, Ah + gA0);
        CP_ASYNC16(s1 + OFF_AH, Ah + gA1);
        CP_ASYNC16(s0 + OFF_AL, Al + gA0);
        CP_ASYNC16(s1 + OFF_AL, Al + gA1);
        CP_ASYNC16(s0 + OFF_BH, Bh + gB0);
        CP_ASYNC16(s1 + OFF_BH, Bh + gB1);
        CP_ASYNC16(s0 + OFF_BL, Bl + gB0);
        CP_ASYNC16(s1 + OFF_BL, Bl + gB1);
    };

    // prologue: fill NSTAGE-1 stages
    load_stage(0, 0); CP_COMMIT();
    load_stage(1, 1); CP_COMMIT();

    int buf = 0;
    for (int c = 0; c < nch; ++c) {
        if (c == nch - 1) { CP_WAIT(0); } else { CP_WAIT(1); }
        __syncthreads();

        const uint32_t sg = sbase + (uint32_t)buf * STAGE_BYTES;
        #pragma unroll
        for (int ks = 0; ks < 4; ++ks) {
            const uint32_t ko = (uint32_t)ks * 32;  // K16 slice = 32 bytes
            uint32_t ah[2][4], al[2][4], bh[4][2], bl[4][2];
            #pragma unroll
            for (int mt = 0; mt < 2; ++mt) {
                uint32_t a = sg + aFragOff + (uint32_t)mt * (16 * ROWB) + ko;
                LDSM4(ah[mt][0], ah[mt][1], ah[mt][2], ah[mt][3], a + OFF_AH);
                LDSM4(al[mt][0], al[mt][1], al[mt][2], al[mt][3], a + OFF_AL);
            }
            #pragma unroll
            for (int ntp = 0; ntp < 2; ++ntp) {
                uint32_t b = sg + bFragOff + (uint32_t)ntp * (16 * ROWB) + ko;
                uint32_t r0, r1, r2, r3;
                LDSM4(r0, r1, r2, r3, b + OFF_BH);
                bh[2 * ntp][0] = r0; bh[2 * ntp][1] = r2;
                bh[2 * ntp + 1][0] = r1; bh[2 * ntp + 1][1] = r3;
                LDSM4(r0, r1, r2, r3, b + OFF_BL);
                bl[2 * ntp][0] = r0; bl[2 * ntp][1] = r2;
                bl[2 * ntp + 1][0] = r1; bl[2 * ntp + 1][1] = r3;
            }
            #pragma unroll
            for (int mt = 0; mt < 2; ++mt)
                #pragma unroll
                for (int nt = 0; nt < 4; ++nt) {
                    MMA16816(acc[mt][nt], ah[mt], bh[nt]);
                    MMA16816(acc[mt][nt], ah[mt], bl[nt]);
                    MMA16816(acc[mt][nt], al[mt], bh[nt]);
                }
        }

        const int nx = c + NSTAGE - 1;
        if (nx < nch) { load_stage(nx, nx % NSTAGE); CP_COMMIT(); }
        buf = (buf + 1 == NSTAGE) ? 0 : buf + 1;
    }

    // ---- epilogue: bias (+relu) fused; split-bf16 or fp32 out ----
    const int mrow = lane >> 2;
    const int ncol = (lane & 3) * 2;
    #pragma unroll
    for (int mt = 0; mt < 2; ++mt) {
        #pragma unroll
        for (int nt = 0; nt < 4; ++nt) {
            const int n = n0 + wn * 32 + nt * 8 + ncol;
            float bx = 0.0f, by = 0.0f;
            if (split_out) {
                float2 bv = *reinterpret_cast<const float2*>(bias + n);
                bx = bv.x; by = bv.y;
            } else {
                if (n     < Nreal) bx = bias[n];
                if (n + 1 < Nreal) by = bias[n + 1];
            }
            #pragma unroll
            for (int half = 0; half < 2; ++half) {
                const int m = m0 + wm * 32 + mt * 16 + mrow + half * 8;
                float v0 = acc[mt][nt][half * 2 + 0] + bx;
                float v1 = acc[mt][nt][half * 2 + 1] + by;
                if (do_relu) {
                    v0 = v0 > 0.0f ? v0 : 0.0f;
                    v1 = v1 > 0.0f ? v1 : 0.0f;
                }
                if (split_out) {
                    __nv_bfloat16 h0, q0, h1, q1;
                    split2(v0, h0, q0); split2(v1, h1, q1);
                    *reinterpret_cast<__nv_bfloat162*>(Ch + (size_t)m * N + n) =
                        __nv_bfloat162(h0, h1);
                    *reinterpret_cast<__nv_bfloat162*>(Cl + (size_t)m * N + n) =
                        __nv_bfloat162(q0, q1);
                } else {
                    if (n     < Nreal) Cf[(size_t)m * Nreal + n]     = v0;
                    if (n + 1 < Nreal) Cf[(size_t)m * Nreal + n + 1] = v1;
                }
            }
        }
    }
}

// ============================================================
// Launch
// ============================================================
extern "C" void kernel_launch(void* const* d_in, const int* in_sizes, int n_in,
                              void* d_out, int out_size)
{
    const float* x  = (const float*)d_in[0];
    const float* w1 = (const float*)d_in[1];
    const float* b1 = (const float*)d_in[2];
    const float* w2 = (const float*)d_in[3];
    const float* b2 = (const float*)d_in[4];
    const float* w3 = (const float*)d_in[5];
    const float* b3 = (const float*)d_in[6];
    float* out = (float*)d_out;

    void *pXh, *pXl, *pW1h, *pW1l, *pW2h, *pW2l, *pW3h, *pW3l, *pH1h, *pH1l, *pH2h, *pH2l;
    cudaGetSymbolAddress(&pXh, g_Xh);   cudaGetSymbolAddress(&pXl, g_Xl);
    cudaGetSymbolAddress(&pW1h, g_W1h); cudaGetSymbolAddress(&pW1l, g_W1l);
    cudaGetSymbolAddress(&pW2h, g_W2h); cudaGetSymbolAddress(&pW2l, g_W2l);
    cudaGetSymbolAddress(&pW3h, g_W3h); cudaGetSymbolAddress(&pW3l, g_W3l);
    cudaGetSymbolAddress(&pH1h, g_H1h); cudaGetSymbolAddress(&pH1l, g_H1l);
    cudaGetSymbolAddress(&pH2h, g_H2h); cudaGetSymbolAddress(&pH2l, g_H2l);

    cudaFuncSetAttribute(gemm_split_kernel,
                         cudaFuncAttributeMaxDynamicSharedMemorySize, SMEM_TOTAL);

    // --- pre-pass: split x; transpose+split weights ---
    {
        int n4 = (BATCH * IN_SZ) / 4;
        split_kernel<<<(n4 + 255) / 256, 256>>>(
            x, (__nv_bfloat16*)pXh, (__nv_bfloat16*)pXl, n4);
    }
    transpose_split_kernel<<<dim3(HID / 32, IN_SZ / 32), dim3(32, 8)>>>(
        w1, (__nv_bfloat16*)pW1h, (__nv_bfloat16*)pW1l, IN_SZ, HID, HID);
    transpose_split_kernel<<<dim3(HID / 32, HID / 32), dim3(32, 8)>>>(
        w2, (__nv_bfloat16*)pW2h, (__nv_bfloat16*)pW2l, HID, HID, HID);
    transpose_split_kernel<<<dim3(NCLSP / 32, HID / 32), dim3(32, 8)>>>(
        w3, (__nv_bfloat16*)pW3h, (__nv_bfloat16*)pW3l, HID, NCLS, NCLSP);

    // --- layer 1: h1 = relu(x @ w1 + b1), split-bf16 out ---
    gemm_split_kernel<<<(BATCH / 128) * (HID / 128), 512, SMEM_TOTAL>>>(
        (const __nv_bfloat16*)pXh, (const __nv_bfloat16*)pXl,
        (const __nv_bfloat16*)pW1h, (const __nv_bfloat16*)pW1l,
        b1, nullptr, (__nv_bfloat16*)pH1h, (__nv_bfloat16*)pH1l,
        BATCH, HID, IN_SZ, HID, 1, 1);

    // --- layer 2: h2 = relu(h1 @ w2 + b2), split-bf16 out ---
    gemm_split_kernel<<<(BATCH / 128) * (HID / 128), 512, SMEM_TOTAL>>>(
        (const __nv_bfloat16*)pH1h, (const __nv_bfloat16*)pH1l,
        (const __nv_bfloat16*)pW2h, (const __nv_bfloat16*)pW2l,
        b2, nullptr, (__nv_bfloat16*)pH2h, (__nv_bfloat16*)pH2l,
        BATCH, HID, HID, HID, 1, 1);

    // --- layer 3: out = h2 @ w3 + b3, fp32 out (N padded 1024 -> 1000) ---
    gemm_split_kernel<<<(BATCH / 128) * (NCLSP / 128), 512, SMEM_TOTAL>>>(
        (const __nv_bfloat16*)pH2h, (const __nv_bfloat16*)pH2l,
        (const __nv_bfloat16*)pW3h, (const __nv_bfloat16*)pW3l,
        b3, out, nullptr, nullptr,
        BATCH, NCLSP, HID, NCLS, 0, 0);
}

// round 11
// speedup vs baseline: 1.7042x; 1.3738x over previous
#include <cuda_runtime.h>
#include <cuda_fp16.h>
#include <cstdint>

// ============================================================
// Problem sizes
// ============================================================
#define BATCH   4096
#define IN_SZ   2048
#define HID     4096
#define NCLS    1000
#define NCLSP   1024   // padded N for layer 3

// ============================================================
// Device scratch (allocation-free rule: __device__ globals)
// Weights: single fp16 (hi). Activations: split fp16 hi+lo.
// ============================================================
__device__ __half g_Xh [(size_t)BATCH * IN_SZ];
__device__ __half g_Xl [(size_t)BATCH * IN_SZ];
__device__ __half g_W1h[(size_t)HID   * IN_SZ];   // [N=HID, K=IN_SZ] K-major
__device__ __half g_W2h[(size_t)HID   * HID];
__device__ __half g_W3h[(size_t)NCLSP * HID];
__device__ __half g_H1h[(size_t)BATCH * HID];
__device__ __half g_H1l[(size_t)BATCH * HID];
__device__ __half g_H2h[(size_t)BATCH * HID];
__device__ __half g_H2l[(size_t)BATCH * HID];

// ============================================================
// Baseline-target PTX helpers (NO a-suffix features)
// ============================================================
__device__ __forceinline__ uint32_t smem_u32(const void* p) {
    uint32_t a;
    asm("{ .reg .u64 t; cvta.to.shared.u64 t, %1; cvt.u32.u64 %0, t; }"
        : "=r"(a) : "l"(p));
    return a;
}

#define CP_ASYNC16(dst, src) \
    asm volatile("cp.async.cg.shared.global [%0], [%1], 16;" \
        :: "r"(dst), "l"(src) : "memory")
#define CP_COMMIT() asm volatile("cp.async.commit_group;" ::: "memory")
#define CP_WAIT(n)  asm volatile("cp.async.wait_group %0;" :: "n"(n) : "memory")

#define LDSM4(r0, r1, r2, r3, addr) \
    asm volatile("ldmatrix.sync.aligned.m8n8.x4.shared.b16 {%0,%1,%2,%3}, [%4];" \
        : "=r"(r0), "=r"(r1), "=r"(r2), "=r"(r3) : "r"(addr))

#define MMA16816(d, a, b) \
    asm volatile("mma.sync.aligned.m16n8k16.row.col.f32.f16.f16.f32 " \
        "{%0,%1,%2,%3}, {%4,%5,%6,%7}, {%8,%9}, {%0,%1,%2,%3};" \
        : "+f"((d)[0]), "+f"((d)[1]), "+f"((d)[2]), "+f"((d)[3]) \
        : "r"((a)[0]), "r"((a)[1]), "r"((a)[2]), "r"((a)[3]), \
          "r"((b)[0]), "r"((b)[1]))

__device__ __forceinline__ void split2h(float v, __half& h, __half& l) {
    h = __float2half_rn(v);
    l = __float2half_rn(v - __half2float(h));
}

// ============================================================
// Pre-pass 1: elementwise split fp32 -> (hi, lo) fp16
// ============================================================
__global__ void __launch_bounds__(256)
split_kernel(const float* __restrict__ in, __half* __restrict__ oh,
             __half* __restrict__ ol, int n4)
{
    int i = blockIdx.x * 256 + threadIdx.x;
    if (i >= n4) return;
    float4 v = reinterpret_cast<const float4*>(in)[i];
    __half h0, h1, h2, h3, l0, l1, l2, l3;
    split2h(v.x, h0, l0); split2h(v.y, h1, l1);
    split2h(v.z, h2, l2); split2h(v.w, h3, l3);
    __half2* oh2 = reinterpret_cast<__half2*>(oh);
    __half2* ol2 = reinterpret_cast<__half2*>(ol);
    oh2[i * 2 + 0] = __half2(h0, h1);
    oh2[i * 2 + 1] = __half2(h2, h3);
    ol2[i * 2 + 0] = __half2(l0, l1);
    ol2[i * 2 + 1] = __half2(l2, l3);
}

// ============================================================
// Pre-pass 2: transpose [K,N] fp32 -> [Npad,K] fp16 (hi only, zero-pad n>=N)
// ============================================================
__global__ void __launch_bounds__(256)
transpose_h_kernel(const float* __restrict__ w, __half* __restrict__ oh,
                   int K, int N, int Npad)
{
    __shared__ float t[32][33];
    int n0 = blockIdx.x * 32;
    int k0 = blockIdx.y * 32;
    #pragma unroll
    for (int r = threadIdx.y; r < 32; r += 8) {
        int n = n0 + threadIdx.x;
        float v = 0.0f;
        if (n < N) v = w[(size_t)(k0 + r) * N + n];
        t[r][threadIdx.x] = v;
    }
    __syncthreads();
    #pragma unroll
    for (int r = threadIdx.y; r < 32; r += 8) {
        int n = n0 + r;
        int k = k0 + threadIdx.x;
        oh[(size_t)n * K + k] = __float2half_rn(t[threadIdx.x][r]);
    }
}

// ============================================================
// GEMM: C[M,N] = op(A @ B^T + bias), fp16 split-A 2-term accumulation
//   A: (Ah,Al) [M,K] K-major fp16;  B: Bh [N,K] K-major fp16
//   D += Ah*Bh + Al*Bh  (dropped term A*(B-Bh) ~ 2^-11 rel)
// CTA tile 128x128, K-chunk 64, 4-stage cp.async pipeline.
// 512 threads = 16 warps in 4(M) x 4(N); warp tile 32x32 (no reg spill).
// SMEM rows padded to 144 B (64 fp16 data + 16 pad) -> conflict-free ldmatrix.
// ============================================================
#define ROWB        144
#define KC          64
#define OFF_AH      0
#define OFF_AL      (128 * ROWB)            // 18432
#define OFF_BH      (2 * 128 * ROWB)        // 36864
#define STAGE_BYTES (3 * 128 * ROWB)        // 55296
#define NSTAGE      4
#define SMEM_TOTAL  (NSTAGE * STAGE_BYTES)  // 221184

__global__ void __launch_bounds__(512, 1)
gemm_split_kernel(const __half* __restrict__ Ah, const __half* __restrict__ Al,
                  const __half* __restrict__ Bh,
                  const float* __restrict__ bias,
                  float* __restrict__ Cf,
                  __half* __restrict__ Ch, __half* __restrict__ Cl,
                  int M, int N, int K, int Nreal, int do_relu, int split_out)
{
    extern __shared__ char smem[];
    const uint32_t sbase = smem_u32(smem);
    const int tid  = threadIdx.x;
    const int wid  = tid >> 5;
    const int lane = tid & 31;
    const int wm   = wid >> 2;   // 0..3
    const int wn   = wid & 3;    // 0..3

    // ---- block swizzle for L2 locality ----
    const int tiles_n = N >> 7;
    const int tiles_m = M >> 7;
    const int G = 8;
    const int bpg = G * tiles_n;
    const int group = blockIdx.x / bpg;
    const int rem = blockIdx.x - group * bpg;
    int gsz = tiles_m - group * G; if (gsz > G) gsz = G;
    const int tm = group * G + rem % gsz;
    const int tn = rem / gsz;
    const int m0 = tm << 7;
    const int n0 = tn << 7;

    // loader mapping: per array 128 rows x 8 cols of 16B; thread covers
    // (row, col) and (row+64, col).
    const int ld_r = tid >> 3;    // 0..63
    const int ld_c = tid & 7;     // 0..7

    // ldmatrix per-lane addressing
    const uint32_t lrow16 = (uint32_t)(lane & 15) * ROWB + (uint32_t)(lane >> 4) * 16;
    const uint32_t aFragOff = (uint32_t)(wm * 32) * ROWB + lrow16;
    const uint32_t bFragOff = (uint32_t)(wn * 32) * ROWB + lrow16;

    float acc[2][4][4];
    #pragma unroll
    for (int mt = 0; mt < 2; ++mt)
        #pragma unroll
        for (int nt = 0; nt < 4; ++nt)
            #pragma unroll
            for (int e = 0; e < 4; ++e) acc[mt][nt][e] = 0.0f;

    const int nch = K / KC;

    auto load_stage = [&](int chunk, int buf) {
        const int kb = chunk * KC;
        const uint32_t s0 = sbase + (uint32_t)buf * STAGE_BYTES
                          + (uint32_t)ld_r * ROWB + (uint32_t)ld_c * 16;
        const uint32_t s1 = s0 + 64 * ROWB;
        const size_t gA0 = (size_t)(m0 + ld_r) * K + kb + ld_c * 8;
        const size_t gA1 = gA0 + (size_t)64 * K;
        const size_t gB0 = (size_t)(n0 + ld_r) * K + kb + ld_c * 8;
        const size_t gB1 = gB0 + (size_t)64 * K;
        CP_ASYNC16(s0 + OFF_AH, Ah + gA0);
        CP_ASYNC16(s1 + OFF_AH, Ah + gA1);
        CP_ASYNC16(s0 + OFF_AL, Al + gA0);
        CP_ASYNC16(s1 + OFF_AL, Al + gA1);
        CP_ASYNC16(s0 + OFF_BH, Bh + gB0);
        CP_ASYNC16(s1 + OFF_BH, Bh + gB1);
    };

    // prologue: fill NSTAGE-1 stages
    load_stage(0, 0); CP_COMMIT();
    load_stage(1, 1); CP_COMMIT();
    load_stage(2, 2); CP_COMMIT();

    int buf = 0;
    for (int c = 0; c < nch; ++c) {
        if (c >= nch - (NSTAGE - 1)) { CP_WAIT(0); }
        else                         { CP_WAIT(NSTAGE - 2); }
        __syncthreads();

        const uint32_t sg = sbase + (uint32_t)buf * STAGE_BYTES;
        #pragma unroll
        for (int ks = 0; ks < 4; ++ks) {
            const uint32_t ko = (uint32_t)ks * 32;  // K16 slice = 32 bytes
            uint32_t ah[2][4], al[2][4], bh[4][2];
            #pragma unroll
            for (int mt = 0; mt < 2; ++mt) {
                uint32_t a = sg + aFragOff + (uint32_t)mt * (16 * ROWB) + ko;
                LDSM4(ah[mt][0], ah[mt][1], ah[mt][2], ah[mt][3], a + OFF_AH);
                LDSM4(al[mt][0], al[mt][1], al[mt][2], al[mt][3], a + OFF_AL);
            }
            #pragma unroll
            for (int ntp = 0; ntp < 2; ++ntp) {
                uint32_t b = sg + bFragOff + (uint32_t)ntp * (16 * ROWB) + ko;
                uint32_t r0, r1, r2, r3;
                LDSM4(r0, r1, r2, r3, b + OFF_BH);
                bh[2 * ntp][0] = r0; bh[2 * ntp][1] = r2;
                bh[2 * ntp + 1][0] = r1; bh[2 * ntp + 1][1] = r3;
            }
            #pragma unroll
            for (int mt = 0; mt < 2; ++mt)
                #pragma unroll
                for (int nt = 0; nt < 4; ++nt) {
                    MMA16816(acc[mt][nt], ah[mt], bh[nt]);
                    MMA16816(acc[mt][nt], al[mt], bh[nt]);
                }
        }

        const int nx = c + NSTAGE - 1;
        if (nx < nch) { load_stage(nx, nx % NSTAGE); CP_COMMIT(); }
        buf = (buf + 1 == NSTAGE) ? 0 : buf + 1;
    }

    // ---- epilogue: bias (+relu) fused; split-fp16 or fp32 out ----
    const int mrow = lane >> 2;
    const int ncol = (lane & 3) * 2;
    #pragma unroll
    for (int mt = 0; mt < 2; ++mt) {
        #pragma unroll
        for (int nt = 0; nt < 4; ++nt) {
            const int n = n0 + wn * 32 + nt * 8 + ncol;
            float bx = 0.0f, by = 0.0f;
            if (split_out) {
                float2 bv = *reinterpret_cast<const float2*>(bias + n);
                bx = bv.x; by = bv.y;
            } else {
                if (n     < Nreal) bx = bias[n];
                if (n + 1 < Nreal) by = bias[n + 1];
            }
            #pragma unroll
            for (int half = 0; half < 2; ++half) {
                const int m = m0 + wm * 32 + mt * 16 + mrow + half * 8;
                float v0 = acc[mt][nt][half * 2 + 0] + bx;
                float v1 = acc[mt][nt][half * 2 + 1] + by;
                if (do_relu) {
                    v0 = v0 > 0.0f ? v0 : 0.0f;
                    v1 = v1 > 0.0f ? v1 : 0.0f;
                }
                if (split_out) {
                    __half h0, q0, h1, q1;
                    split2h(v0, h0, q0); split2h(v1, h1, q1);
                    *reinterpret_cast<__half2*>(Ch + (size_t)m * N + n) =
                        __half2(h0, h1);
                    *reinterpret_cast<__half2*>(Cl + (size_t)m * N + n) =
                        __half2(q0, q1);
                } else {
                    if (n     < Nreal) Cf[(size_t)m * Nreal + n]     = v0;
                    if (n + 1 < Nreal) Cf[(size_t)m * Nreal + n + 1] = v1;
                }
            }
        }
    }
}

// ============================================================
// Launch
// ============================================================
extern "C" void kernel_launch(void* const* d_in, const int* in_sizes, int n_in,
                              void* d_out, int out_size)
{
    const float* x  = (const float*)d_in[0];
    const float* w1 = (const float*)d_in[1];
    const float* b1 = (const float*)d_in[2];
    const float* w2 = (const float*)d_in[3];
    const float* b2 = (const float*)d_in[4];
    const float* w3 = (const float*)d_in[5];
    const float* b3 = (const float*)d_in[6];
    float* out = (float*)d_out;

    void *pXh, *pXl, *pW1h, *pW2h, *pW3h, *pH1h, *pH1l, *pH2h, *pH2l;
    cudaGetSymbolAddress(&pXh, g_Xh);   cudaGetSymbolAddress(&pXl, g_Xl);
    cudaGetSymbolAddress(&pW1h, g_W1h);
    cudaGetSymbolAddress(&pW2h, g_W2h);
    cudaGetSymbolAddress(&pW3h, g_W3h);
    cudaGetSymbolAddress(&pH1h, g_H1h); cudaGetSymbolAddress(&pH1l, g_H1l);
    cudaGetSymbolAddress(&pH2h, g_H2h); cudaGetSymbolAddress(&pH2l, g_H2l);

    cudaFuncSetAttribute(gemm_split_kernel,
                         cudaFuncAttributeMaxDynamicSharedMemorySize, SMEM_TOTAL);

    // --- pre-pass: split x; transpose weights to fp16 hi ---
    {
        int n4 = (BATCH * IN_SZ) / 4;
        split_kernel<<<(n4 + 255) / 256, 256>>>(
            x, (__half*)pXh, (__half*)pXl, n4);
    }
    transpose_h_kernel<<<dim3(HID / 32, IN_SZ / 32), dim3(32, 8)>>>(
        w1, (__half*)pW1h, IN_SZ, HID, HID);
    transpose_h_kernel<<<dim3(HID / 32, HID / 32), dim3(32, 8)>>>(
        w2, (__half*)pW2h, HID, HID, HID);
    transpose_h_kernel<<<dim3(NCLSP / 32, HID / 32), dim3(32, 8)>>>(
        w3, (__half*)pW3h, HID, NCLS, NCLSP);

    // --- layer 1: h1 = relu(x @ w1 + b1), split-fp16 out ---
    gemm_split_kernel<<<(BATCH / 128) * (HID / 128), 512, SMEM_TOTAL>>>(
        (const __half*)pXh, (const __half*)pXl, (const __half*)pW1h,
        b1, nullptr, (__half*)pH1h, (__half*)pH1l,
        BATCH, HID, IN_SZ, HID, 1, 1);

    // --- layer 2: h2 = relu(h1 @ w2 + b2), split-fp16 out ---
    gemm_split_kernel<<<(BATCH / 128) * (HID / 128), 512, SMEM_TOTAL>>>(
        (const __half*)pH1h, (const __half*)pH1l, (const __half*)pW2h,
        b2, nullptr, (__half*)pH2h, (__half*)pH2l,
        BATCH, HID, HID, HID, 1, 1);

    // --- layer 3: out = h2 @ w3 + b3, fp32 out (N padded 1024 -> 1000) ---
    gemm_split_kernel<<<(BATCH / 128) * (NCLSP / 128), 512, SMEM_TOTAL>>>(
        (const __half*)pH2h, (const __half*)pH2l, (const __half*)pW3h,
        b3, out, nullptr, nullptr,
        BATCH, NCLSP, HID, NCLS, 0, 0);
}

// round 13
// speedup vs baseline: 2.6009x; 1.5262x over previous
#include <cuda_runtime.h>
#include <cuda_fp16.h>
#include <cstdint>

// ============================================================
// Problem sizes
// ============================================================
#define BATCH   4096
#define IN_SZ   2048
#define HID     4096
#define NCLS    1000
#define NCLSP   1024   // padded N for layer 3

// ============================================================
// Device scratch (allocation-free rule: __device__ globals)
// Pure fp16: weights and activations single-plane.
// ============================================================
__device__ __half g_X  [(size_t)BATCH * IN_SZ];
__device__ __half g_W1 [(size_t)HID   * IN_SZ];   // [N=HID, K=IN_SZ] K-major
__device__ __half g_W2 [(size_t)HID   * HID];
__device__ __half g_W3 [(size_t)NCLSP * HID];
__device__ __half g_H1 [(size_t)BATCH * HID];
__device__ __half g_H2 [(size_t)BATCH * HID];

// ============================================================
// Baseline-target PTX helpers (NO a-suffix features)
// ============================================================
__device__ __forceinline__ uint32_t smem_u32(const void* p) {
    uint32_t a;
    asm("{ .reg .u64 t; cvta.to.shared.u64 t, %1; cvt.u32.u64 %0, t; }"
        : "=r"(a) : "l"(p));
    return a;
}

#define CP_ASYNC16(dst, src) \
    asm volatile("cp.async.cg.shared.global [%0], [%1], 16;" \
        :: "r"(dst), "l"(src) : "memory")
#define CP_COMMIT() asm volatile("cp.async.commit_group;" ::: "memory")
#define CP_WAIT(n)  asm volatile("cp.async.wait_group %0;" :: "n"(n) : "memory")

#define LDSM4(r0, r1, r2, r3, addr) \
    asm volatile("ldmatrix.sync.aligned.m8n8.x4.shared.b16 {%0,%1,%2,%3}, [%4];" \
        : "=r"(r0), "=r"(r1), "=r"(r2), "=r"(r3) : "r"(addr))

#define MMA16816(d, a, b) \
    asm volatile("mma.sync.aligned.m16n8k16.row.col.f32.f16.f16.f32 " \
        "{%0,%1,%2,%3}, {%4,%5,%6,%7}, {%8,%9}, {%0,%1,%2,%3};" \
        : "+f"((d)[0]), "+f"((d)[1]), "+f"((d)[2]), "+f"((d)[3]) \
        : "r"((a)[0]), "r"((a)[1]), "r"((a)[2]), "r"((a)[3]), \
          "r"((b)[0]), "r"((b)[1]))

// ============================================================
// Pre-pass 1: elementwise convert fp32 -> fp16
// ============================================================
__global__ void __launch_bounds__(256)
convert_kernel(const float* __restrict__ in, __half* __restrict__ o, int n4)
{
    int i = blockIdx.x * 256 + threadIdx.x;
    if (i >= n4) return;
    float4 v = reinterpret_cast<const float4*>(in)[i];
    __half2* o2 = reinterpret_cast<__half2*>(o);
    o2[i * 2 + 0] = __half2(__float2half_rn(v.x), __float2half_rn(v.y));
    o2[i * 2 + 1] = __half2(__float2half_rn(v.z), __float2half_rn(v.w));
}

// ============================================================
// Pre-pass 2: transpose [K,N] fp32 -> [Npad,K] fp16 (zero-pad n>=N)
// ============================================================
__global__ void __launch_bounds__(256)
transpose_h_kernel(const float* __restrict__ w, __half* __restrict__ oh,
                   int K, int N, int Npad)
{
    __shared__ float t[32][33];
    int n0 = blockIdx.x * 32;
    int k0 = blockIdx.y * 32;
    #pragma unroll
    for (int r = threadIdx.y; r < 32; r += 8) {
        int n = n0 + threadIdx.x;
        float v = 0.0f;
        if (n < N) v = w[(size_t)(k0 + r) * N + n];
        t[r][threadIdx.x] = v;
    }
    __syncthreads();
    #pragma unroll
    for (int r = threadIdx.y; r < 32; r += 8) {
        int n = n0 + r;
        int k = k0 + threadIdx.x;
        oh[(size_t)n * K + k] = __float2half_rn(t[threadIdx.x][r]);
    }
}

// ============================================================
// GEMM: C[M,N] = op(A @ B^T + bias), pure fp16, fp32 accumulate
//   A: [M,K] K-major fp16;  B: [N,K] K-major fp16
// CTA tile 128x128, K-chunk 128, 3-stage cp.async pipeline.
// 512 threads = 16 warps in 4(M) x 4(N); warp tile 32x32.
// SMEM rows padded to 272 B (128 fp16 data + 16 pad):
//   r*272 mod 128 = 16r -> 8 distinct 16B slots per 8-row ldmatrix phase.
// ============================================================
#define ROWB        272
#define KC          128
#define OFF_A       0
#define OFF_B       (128 * ROWB)            // 34816
#define STAGE_BYTES (2 * 128 * ROWB)        // 69632
#define NSTAGE      3
#define SMEM_TOTAL  (NSTAGE * STAGE_BYTES)  // 208896

__global__ void __launch_bounds__(512, 1)
gemm_h_kernel(const __half* __restrict__ A, const __half* __restrict__ B,
              const float* __restrict__ bias,
              float* __restrict__ Cf, __half* __restrict__ Ch,
              int M, int N, int K, int Nreal, int do_relu, int h_out)
{
    extern __shared__ char smem[];
    const uint32_t sbase = smem_u32(smem);
    const int tid  = threadIdx.x;
    const int wid  = tid >> 5;
    const int lane = tid & 31;
    const int wm   = wid >> 2;   // 0..3
    const int wn   = wid & 3;    // 0..3

    // ---- block swizzle for L2 locality ----
    const int tiles_n = N >> 7;
    const int tiles_m = M >> 7;
    const int G = 8;
    const int bpg = G * tiles_n;
    const int group = blockIdx.x / bpg;
    const int rem = blockIdx.x - group * bpg;
    int gsz = tiles_m - group * G; if (gsz > G) gsz = G;
    const int tm = group * G + rem % gsz;
    const int tn = rem / gsz;
    const int m0 = tm << 7;
    const int n0 = tn << 7;

    // loader mapping: per array 128 rows x 16 cols of 16B.
    // thread covers row = tid>>2, cols (tid&3) + 4j, j = 0..3.
    const int ld_r = tid >> 2;    // 0..127
    const int ld_c = tid & 3;     // 0..3

    // ldmatrix per-lane addressing
    const uint32_t lrow16 = (uint32_t)(lane & 15) * ROWB + (uint32_t)(lane >> 4) * 16;
    const uint32_t aFragOff = (uint32_t)(wm * 32) * ROWB + lrow16;
    const uint32_t bFragOff = (uint32_t)(wn * 32) * ROWB + lrow16;

    float acc[2][4][4];
    #pragma unroll
    for (int mt = 0; mt < 2; ++mt)
        #pragma unroll
        for (int nt = 0; nt < 4; ++nt)
            #pragma unroll
            for (int e = 0; e < 4; ++e) acc[mt][nt][e] = 0.0f;

    const int nch = K / KC;

    auto load_stage = [&](int chunk, int buf) {
        const int kb = chunk * KC;
        const uint32_t s0 = sbase + (uint32_t)buf * STAGE_BYTES
                          + (uint32_t)ld_r * ROWB + (uint32_t)ld_c * 16;
        const size_t gA = (size_t)(m0 + ld_r) * K + kb + ld_c * 8;
        const size_t gB = (size_t)(n0 + ld_r) * K + kb + ld_c * 8;
        #pragma unroll
        for (int j = 0; j < 4; ++j) {
            CP_ASYNC16(s0 + OFF_A + j * 64, A + gA + j * 32);
            CP_ASYNC16(s0 + OFF_B + j * 64, B + gB + j * 32);
        }
    };

    // prologue: fill NSTAGE-1 stages
    load_stage(0, 0); CP_COMMIT();
    load_stage(1, 1); CP_COMMIT();

    int buf = 0;
    for (int c = 0; c < nch; ++c) {
        if (c >= nch - (NSTAGE - 1)) { CP_WAIT(0); }
        else                         { CP_WAIT(NSTAGE - 2); }
        __syncthreads();

        const uint32_t sg = sbase + (uint32_t)buf * STAGE_BYTES;
        #pragma unroll
        for (int ks = 0; ks < 8; ++ks) {
            const uint32_t ko = (uint32_t)ks * 32;  // K16 slice = 32 bytes
            uint32_t ah[2][4], bh[4][2];
            #pragma unroll
            for (int mt = 0; mt < 2; ++mt) {
                uint32_t a = sg + aFragOff + (uint32_t)mt * (16 * ROWB) + ko;
                LDSM4(ah[mt][0], ah[mt][1], ah[mt][2], ah[mt][3], a + OFF_A);
            }
            #pragma unroll
            for (int ntp = 0; ntp < 2; ++ntp) {
                uint32_t b = sg + bFragOff + (uint32_t)ntp * (16 * ROWB) + ko;
                uint32_t r0, r1, r2, r3;
                LDSM4(r0, r1, r2, r3, b + OFF_B);
                bh[2 * ntp][0] = r0; bh[2 * ntp][1] = r2;
                bh[2 * ntp + 1][0] = r1; bh[2 * ntp + 1][1] = r3;
            }
            #pragma unroll
            for (int mt = 0; mt < 2; ++mt)
                #pragma unroll
                for (int nt = 0; nt < 4; ++nt)
                    MMA16816(acc[mt][nt], ah[mt], bh[nt]);
        }

        const int nx = c + NSTAGE - 1;
        if (nx < nch) { load_stage(nx, nx % NSTAGE); CP_COMMIT(); }
        buf = (buf + 1 == NSTAGE) ? 0 : buf + 1;
    }

    // ---- epilogue: bias (+relu) fused; fp16 or fp32 out ----
    const int mrow = lane >> 2;
    const int ncol = (lane & 3) * 2;
    #pragma unroll
    for (int mt = 0; mt < 2; ++mt) {
        #pragma unroll
        for (int nt = 0; nt < 4; ++nt) {
            const int n = n0 + wn * 32 + nt * 8 + ncol;
            float bx = 0.0f, by = 0.0f;
            if (h_out) {
                float2 bv = *reinterpret_cast<const float2*>(bias + n);
                bx = bv.x; by = bv.y;
            } else {
                if (n     < Nreal) bx = bias[n];
                if (n + 1 < Nreal) by = bias[n + 1];
            }
            #pragma unroll
            for (int half = 0; half < 2; ++half) {
                const int m = m0 + wm * 32 + mt * 16 + mrow + half * 8;
                float v0 = acc[mt][nt][half * 2 + 0] + bx;
                float v1 = acc[mt][nt][half * 2 + 1] + by;
                if (do_relu) {
                    v0 = v0 > 0.0f ? v0 : 0.0f;
                    v1 = v1 > 0.0f ? v1 : 0.0f;
                }
                if (h_out) {
                    *reinterpret_cast<__half2*>(Ch + (size_t)m * N + n) =
                        __half2(__float2half_rn(v0), __float2half_rn(v1));
                } else {
                    if (n     < Nreal) Cf[(size_t)m * Nreal + n]     = v0;
                    if (n + 1 < Nreal) Cf[(size_t)m * Nreal + n + 1] = v1;
                }
            }
        }
    }
}

// ============================================================
// Launch
// ============================================================
extern "C" void kernel_launch(void* const* d_in, const int* in_sizes, int n_in,
                              void* d_out, int out_size)
{
    const float* x  = (const float*)d_in[0];
    const float* w1 = (const float*)d_in[1];
    const float* b1 = (const float*)d_in[2];
    const float* w2 = (const float*)d_in[3];
    const float* b2 = (const float*)d_in[4];
    const float* w3 = (const float*)d_in[5];
    const float* b3 = (const float*)d_in[6];
    float* out = (float*)d_out;

    void *pX, *pW1, *pW2, *pW3, *pH1, *pH2;
    cudaGetSymbolAddress(&pX,  g_X);
    cudaGetSymbolAddress(&pW1, g_W1);
    cudaGetSymbolAddress(&pW2, g_W2);
    cudaGetSymbolAddress(&pW3, g_W3);
    cudaGetSymbolAddress(&pH1, g_H1);
    cudaGetSymbolAddress(&pH2, g_H2);

    cudaFuncSetAttribute(gemm_h_kernel,
                         cudaFuncAttributeMaxDynamicSharedMemorySize, SMEM_TOTAL);

    // --- pre-pass: convert x; transpose weights to fp16 ---
    {
        int n4 = (BATCH * IN_SZ) / 4;
        convert_kernel<<<(n4 + 255) / 256, 256>>>(x, (__half*)pX, n4);
    }
    transpose_h_kernel<<<dim3(HID / 32, IN_SZ / 32), dim3(32, 8)>>>(
        w1, (__half*)pW1, IN_SZ, HID, HID);
    transpose_h_kernel<<<dim3(HID / 32, HID / 32), dim3(32, 8)>>>(
        w2, (__half*)pW2, HID, HID, HID);
    transpose_h_kernel<<<dim3(NCLSP / 32, HID / 32), dim3(32, 8)>>>(
        w3, (__half*)pW3, HID, NCLS, NCLSP);

    // --- layer 1: h1 = relu(x @ w1 + b1), fp16 out ---
    gemm_h_kernel<<<(BATCH / 128) * (HID / 128), 512, SMEM_TOTAL>>>(
        (const __half*)pX, (const __half*)pW1,
        b1, nullptr, (__half*)pH1,
        BATCH, HID, IN_SZ, HID, 1, 1);

    // --- layer 2: h2 = relu(h1 @ w2 + b2), fp16 out ---
    gemm_h_kernel<<<(BATCH / 128) * (HID / 128), 512, SMEM_TOTAL>>>(
        (const __half*)pH1, (const __half*)pW2,
        b2, nullptr, (__half*)pH2,
        BATCH, HID, HID, HID, 1, 1);

    // --- layer 3: out = h2 @ w3 + b3, fp32 out (N padded 1024 -> 1000) ---
    gemm_h_kernel<<<(BATCH / 128) * (NCLSP / 128), 512, SMEM_TOTAL>>>(
        (const __half*)pH2, (const __half*)pW3,
        b3, out, nullptr,
        BATCH, NCLSP, HID, NCLS, 0, 0);
}